// round 10
// baseline (speedup 1.0000x reference)
#include <cuda_runtime.h>
#include <cstdint>

#define MAX_N 100000
#define MAX_E 1200000
#define FDIM 64

__device__ float g_Q[(size_t)MAX_N * FDIM];      // Q = X@W1 + (X*X)@W2
__device__ int   g_cnt[MAX_N];                   // per-row edge count
__device__ int   g_rowstart[MAX_N];              // exclusive scan of g_cnt
__device__ int   g_cursor[MAX_N];                // scatter cursor (== row end after)
__device__ int2  g_edges[MAX_E];                 // binned (col, val) per row
__device__ int   g_bsum[128];                    // block sums for the scan

// ---- TF32 helpers (legacy mma.sync path -> HMMA on sm_103a) ----
__device__ __forceinline__ uint32_t f2tf32(float f) {
    uint32_t u; asm("cvt.rna.tf32.f32 %0, %1;" : "=r"(u) : "f"(f)); return u;
}
__device__ __forceinline__ void mma_tf32(float c[4],
    uint32_t a0, uint32_t a1, uint32_t a2, uint32_t a3,
    uint32_t b0, uint32_t b1)
{
    asm("mma.sync.aligned.m16n8k8.row.col.f32.tf32.tf32.f32 "
        "{%0,%1,%2,%3}, {%4,%5,%6,%7}, {%8,%9}, {%0,%1,%2,%3};"
        : "+f"(c[0]), "+f"(c[1]), "+f"(c[2]), "+f"(c[3])
        : "r"(a0), "r"(a1), "r"(a2), "r"(a3), "r"(b0), "r"(b1));
}

#define XS_STRIDE 68   // 128 rows x 68 floats: banks (4*gi+tk) all distinct
#define WT_STRIDE 68   // W^T [n][k], 64 rows x 68: conflict-free B-frag loads

// ---------------------------------------------------------------------------
// Dense GEMM on tensor cores (tf32) + fused edge histogram.
//   acc1 = X @ W1          -> out = acc1 + (b1+b2)
//   acc2 = (X*X) @ W2      -> Q   = acc1 + acc2
// 256 thr = 8 warps; warp owns 16 rows x 64 cols; block tile = 128 rows.
// A(x^2) fragments = elementwise square of A(x) fragments (no extra reads).
// ---------------------------------------------------------------------------
__global__ __launch_bounds__(256, 2) void gnn_dense_hist(
    const float* __restrict__ X,
    const float* __restrict__ W1, const float* __restrict__ b1,
    const float* __restrict__ W2, const float* __restrict__ b2,
    const int* __restrict__ rows,
    float* __restrict__ out, int N, int E)
{
    extern __shared__ char smraw[];
    float*    Xs  = (float*)smraw;                          // 128*68*4 = 34816
    uint32_t* W1t = (uint32_t*)(smraw + 34816);             // 64*68*4 = 17408
    uint32_t* W2t = (uint32_t*)(smraw + 34816 + 17408);     // 17408  (total 69632)

    const int tid = threadIdx.x;

    // W^T in tf32: Wt[n*68 + k] = tf32(W[k*64 + n])
    for (int i = tid; i < 4096; i += 256) {
        const int n = i >> 6, k = i & 63;
        W1t[n * WT_STRIDE + k] = f2tf32(__ldg(W1 + k * 64 + n));
        W2t[n * WT_STRIDE + k] = f2tf32(__ldg(W2 + k * 64 + n));
    }

    const int row0 = blockIdx.x * 128;
    #pragma unroll
    for (int i = tid; i < 128 * 16; i += 256) {
        const int r  = i >> 4;
        const int gr = row0 + r;
        float4 v = make_float4(0.f, 0.f, 0.f, 0.f);
        if (gr < N) v = reinterpret_cast<const float4*>(X)[(size_t)gr * 16 + (i & 15)];
        reinterpret_cast<float4*>(Xs + r * XS_STRIDE)[i & 15] = v;
    }

    // Fused histogram (memory-pipe; hides under tensor/LDS work below).
    const int stride = gridDim.x * 256;
    for (int e = blockIdx.x * 256 + tid; e < E; e += stride)
        atomicAdd(&g_cnt[__ldg(rows + e)], 1);

    __syncthreads();

    const int wid  = tid >> 5, lane = tid & 31;
    const int gi   = lane >> 2;        // 0..7
    const int tk   = lane & 3;         // 0..3
    const int rA   = wid * 16 + gi;    // A-frag row (first half)

    float acc1[8][4], acc2[8][4];
    #pragma unroll
    for (int t = 0; t < 8; ++t)
        #pragma unroll
        for (int j = 0; j < 4; ++j) { acc1[t][j] = 0.f; acc2[t][j] = 0.f; }

    #pragma unroll
    for (int kk = 0; kk < 8; ++kk) {
        const int k0 = kk * 8 + tk;
        const float x0 = Xs[rA * XS_STRIDE + k0];
        const float x1 = Xs[(rA + 8) * XS_STRIDE + k0];
        const float x2 = Xs[rA * XS_STRIDE + k0 + 4];
        const float x3 = Xs[(rA + 8) * XS_STRIDE + k0 + 4];
        const uint32_t ax0 = f2tf32(x0), ax1 = f2tf32(x1);
        const uint32_t ax2 = f2tf32(x2), ax3 = f2tf32(x3);
        const uint32_t sx0 = f2tf32(x0 * x0), sx1 = f2tf32(x1 * x1);
        const uint32_t sx2 = f2tf32(x2 * x2), sx3 = f2tf32(x3 * x3);

        #pragma unroll
        for (int nt = 0; nt < 8; ++nt) {
            const int col = nt * 8 + gi;
            const uint32_t b10 = W1t[col * WT_STRIDE + k0];
            const uint32_t b11 = W1t[col * WT_STRIDE + k0 + 4];
            const uint32_t b20 = W2t[col * WT_STRIDE + k0];
            const uint32_t b21 = W2t[col * WT_STRIDE + k0 + 4];
            mma_tf32(acc1[nt], ax0, ax1, ax2, ax3, b10, b11);
            mma_tf32(acc2[nt], sx0, sx1, sx2, sx3, b20, b21);
        }
    }

    // Epilogue: C-frag (r, 2c) layout -> float2 stores.
    const int gr0 = row0 + wid * 16 + gi;
    const int gr1 = gr0 + 8;
    #pragma unroll
    for (int nt = 0; nt < 8; ++nt) {
        const int c = nt * 8 + tk * 2;
        const float bbx = __ldg(b1 + c)     + __ldg(b2 + c);
        const float bby = __ldg(b1 + c + 1) + __ldg(b2 + c + 1);
        if (gr0 < N) {
            float2 o = make_float2(acc1[nt][0] + bbx, acc1[nt][1] + bby);
            float2 q = make_float2(acc1[nt][0] + acc2[nt][0],
                                   acc1[nt][1] + acc2[nt][1]);
            *reinterpret_cast<float2*>(out + (size_t)gr0 * 64 + c) = o;
            *reinterpret_cast<float2*>(g_Q + (size_t)gr0 * 64 + c) = q;
        }
        if (gr1 < N) {
            float2 o = make_float2(acc1[nt][2] + bbx, acc1[nt][3] + bby);
            float2 q = make_float2(acc1[nt][2] + acc2[nt][2],
                                   acc1[nt][3] + acc2[nt][3]);
            *reinterpret_cast<float2*>(out + (size_t)gr1 * 64 + c) = o;
            *reinterpret_cast<float2*>(g_Q + (size_t)gr1 * 64 + c) = q;
        }
    }
}

// ---------------------------------------------------------------------------
// Scan stage (R6/R8 measured-best)
// ---------------------------------------------------------------------------
__device__ __forceinline__ int warp_incl_scan(int v) {
    #pragma unroll
    for (int off = 1; off < 32; off <<= 1) {
        int u = __shfl_up_sync(0xffffffffu, v, off);
        if ((threadIdx.x & 31) >= off) v += u;
    }
    return v;
}

__global__ __launch_bounds__(1024) void scan_blocksums(int N) {
    const int i = blockIdx.x * 1024 + threadIdx.x;
    int v = (i < N) ? g_cnt[i] : 0;
    #pragma unroll
    for (int off = 16; off > 0; off >>= 1)
        v += __shfl_down_sync(0xffffffffu, v, off);
    __shared__ int ws[32];
    const int lane = threadIdx.x & 31, wid = threadIdx.x >> 5;
    if (lane == 0) ws[wid] = v;
    __syncthreads();
    if (wid == 0) {
        int x = ws[lane];
        #pragma unroll
        for (int off = 16; off > 0; off >>= 1)
            x += __shfl_down_sync(0xffffffffu, x, off);
        if (lane == 0) g_bsum[blockIdx.x] = x;
    }
}

__global__ __launch_bounds__(128) void scan_bsums(int nb) {
    __shared__ int s[128];
    const int t = threadIdx.x;
    s[t] = (t < nb) ? g_bsum[t] : 0;
    __syncthreads();
    #pragma unroll
    for (int off = 1; off < 128; off <<= 1) {
        int v = (t >= off) ? s[t - off] : 0;
        __syncthreads();
        s[t] += v;
        __syncthreads();
    }
    if (t < nb) g_bsum[t] = s[t];
}

__global__ __launch_bounds__(1024) void scan_write(int N) {
    const int t = threadIdx.x, b = blockIdx.x;
    const int i = b * 1024 + t;
    const int v = (i < N) ? g_cnt[i] : 0;
    const int lane = t & 31, wid = t >> 5;
    int inc = warp_incl_scan(v);
    __shared__ int ws[32];
    if (lane == 31) ws[wid] = inc;
    __syncthreads();
    if (wid == 0) {
        int x = ws[lane];
        x = warp_incl_scan(x);
        ws[lane] = x;
    }
    __syncthreads();
    int excl = inc - v + (wid ? ws[wid - 1] : 0) + (b ? g_bsum[b - 1] : 0);
    if (i < N) { g_rowstart[i] = excl; g_cursor[i] = excl; }
}

__global__ __launch_bounds__(256) void gnn_scatter(
    const int* __restrict__ rows,
    const int* __restrict__ cols,
    const float* __restrict__ vals, int E)
{
    const int e = blockIdx.x * blockDim.x + threadIdx.x;
    if (e >= E) return;
    const int r   = __ldg(rows + e);
    const int pos = atomicAdd(&g_cursor[r], 1);
    g_edges[pos] = make_int2(__ldg(cols + e), __float_as_int(__ldg(vals + e)));
}

// ---------------------------------------------------------------------------
// CSR SpMM: 16 lanes per row, float4 per lane. (identical to R6/R8)
// ---------------------------------------------------------------------------
__global__ __launch_bounds__(256) void gnn_spmm_csr(float* __restrict__ out, int N)
{
    const int gid = blockIdx.x * blockDim.x + threadIdx.x;
    const int row = gid >> 4;
    if (row >= N) return;
    const int lane16 = gid & 15;

    const int start = __ldg(g_rowstart + row);
    const int end   = __ldg(g_cursor + row);
    if (end <= start) return;

    const float4* __restrict__ Q4 = reinterpret_cast<const float4*>(g_Q);
    float4 acc = make_float4(0.f, 0.f, 0.f, 0.f);

    int j = start;
    for (; j + 3 < end; j += 4) {
        const int2 cv0 = __ldg(g_edges + j);
        const int2 cv1 = __ldg(g_edges + j + 1);
        const int2 cv2 = __ldg(g_edges + j + 2);
        const int2 cv3 = __ldg(g_edges + j + 3);
        const float4 q0 = __ldg(Q4 + (size_t)cv0.x * 16 + lane16);
        const float4 q1 = __ldg(Q4 + (size_t)cv1.x * 16 + lane16);
        const float4 q2 = __ldg(Q4 + (size_t)cv2.x * 16 + lane16);
        const float4 q3 = __ldg(Q4 + (size_t)cv3.x * 16 + lane16);
        const float v0 = __int_as_float(cv0.y);
        const float v1 = __int_as_float(cv1.y);
        const float v2 = __int_as_float(cv2.y);
        const float v3 = __int_as_float(cv3.y);
        acc.x = fmaf(v0, q0.x, acc.x); acc.y = fmaf(v0, q0.y, acc.y);
        acc.z = fmaf(v0, q0.z, acc.z); acc.w = fmaf(v0, q0.w, acc.w);
        acc.x = fmaf(v1, q1.x, acc.x); acc.y = fmaf(v1, q1.y, acc.y);
        acc.z = fmaf(v1, q1.z, acc.z); acc.w = fmaf(v1, q1.w, acc.w);
        acc.x = fmaf(v2, q2.x, acc.x); acc.y = fmaf(v2, q2.y, acc.y);
        acc.z = fmaf(v2, q2.z, acc.z); acc.w = fmaf(v2, q2.w, acc.w);
        acc.x = fmaf(v3, q3.x, acc.x); acc.y = fmaf(v3, q3.y, acc.y);
        acc.z = fmaf(v3, q3.z, acc.z); acc.w = fmaf(v3, q3.w, acc.w);
    }
    for (; j < end; ++j) {
        const int2 cv = __ldg(g_edges + j);
        const float4 q = __ldg(Q4 + (size_t)cv.x * 16 + lane16);
        const float v = __int_as_float(cv.y);
        acc.x = fmaf(v, q.x, acc.x); acc.y = fmaf(v, q.y, acc.y);
        acc.z = fmaf(v, q.z, acc.z); acc.w = fmaf(v, q.w, acc.w);
    }

    float4* orow = reinterpret_cast<float4*>(out) + (size_t)row * 16 + lane16;
    float4 o = *orow;
    o.x += acc.x; o.y += acc.y; o.z += acc.z; o.w += acc.w;
    *orow = o;
}

extern "C" void kernel_launch(void* const* d_in, const int* in_sizes, int n_in,
                              void* d_out, int out_size)
{
    const int*   rows = (const int*)  d_in[0];
    const int*   cols = (const int*)  d_in[1];
    const float* vals = (const float*)d_in[2];
    const float* X    = (const float*)d_in[3];
    const float* W1   = (const float*)d_in[4];
    const float* b1   = (const float*)d_in[5];
    const float* W2   = (const float*)d_in[6];
    const float* b2   = (const float*)d_in[7];
    float* out = (float*)d_out;

    const int E = in_sizes[0];
    const int N = in_sizes[3] / FDIM;

    cudaFuncSetAttribute(gnn_dense_hist, cudaFuncAttributeMaxDynamicSharedMemorySize, 69632);

    void* p = nullptr;
    cudaGetSymbolAddress(&p, g_cnt);
    cudaMemsetAsync(p, 0, (size_t)N * sizeof(int));

    const int blocksD = (N + 127) / 128;
    gnn_dense_hist<<<blocksD, 256, 69632>>>(X, W1, b1, W2, b2, rows, out, N, E);

    const int nb = (N + 1023) / 1024;
    scan_blocksums<<<nb, 1024>>>(N);
    scan_bsums<<<1, 128>>>(nb);
    scan_write<<<nb, 1024>>>(N);

    gnn_scatter<<<(E + 255) / 256, 256>>>(rows, cols, vals, E);

    const long long work = (long long)N * 16;
    gnn_spmm_csr<<<(int)((work + 255) / 256), 256>>>(out, N);
}

// round 11
// speedup vs baseline: 1.0628x; 1.0628x over previous
#include <cuda_runtime.h>

#define MAX_N 100000
#define MAX_E 1200000
#define FDIM 64

__device__ float g_Q[(size_t)MAX_N * FDIM];      // Q = X@W1 + (X*X)@W2
__device__ int   g_cnt[MAX_N];                   // per-row edge count
__device__ int   g_rowstart[MAX_N];              // exclusive scan of g_cnt
__device__ int   g_cursor[MAX_N];                // scatter cursor (== row end after)
__device__ int2  g_edges[MAX_E];                 // binned (col, val) per row
__device__ int   g_bsum[128];                    // per-block totals
__device__ int   g_bar;                          // spin-barrier counter (memset 0)

// ---- packed f32x2 helpers (sm_103a FFMA2: 2 fp32 FMAs / issue slot) ----
typedef unsigned long long u64;
__device__ __forceinline__ u64 pack2(float lo, float hi) {
    u64 r; asm("mov.b64 %0, {%1, %2};" : "=l"(r) : "f"(lo), "f"(hi)); return r;
}
__device__ __forceinline__ void unpack2(u64 p, float& lo, float& hi) {
    asm("mov.b64 {%0, %1}, %2;" : "=f"(lo), "=f"(hi) : "l"(p));
}
__device__ __forceinline__ u64 fma2(u64 a, u64 b, u64 c) {
    u64 d; asm("fma.rn.f32x2 %0, %1, %2, %3;" : "=l"(d) : "l"(a), "l"(b), "l"(c)); return d;
}
__device__ __forceinline__ u64 mul2(u64 a, u64 b) {
    u64 d; asm("mul.rn.f32x2 %0, %1, %2;" : "=l"(d) : "l"(a), "l"(b)); return d;
}

// ---------------------------------------------------------------------------
// Dense GEMM (f32x2) + fused histogram. 64-row tile, 4 rows/thread,
// 48KB smem, 3 blocks/SM. (R8 measured-best, byte-identical)
// ---------------------------------------------------------------------------
__global__ __launch_bounds__(256, 3) void gnn_dense_hist(
    const float* __restrict__ X,
    const float* __restrict__ W1, const float* __restrict__ b1,
    const float* __restrict__ W2, const float* __restrict__ b2,
    const int* __restrict__ rows,
    float* __restrict__ out, int N, int E)
{
    extern __shared__ float smem[];
    float* W1s = smem;          // 64*64 = 16KB
    float* W2s = smem + 4096;   // 16KB
    float* Xs  = smem + 8192;   // 64*64 = 16KB

    const int tid = threadIdx.x;

    #pragma unroll
    for (int i = tid; i < 1024; i += 256) {
        reinterpret_cast<float4*>(W1s)[i] = reinterpret_cast<const float4*>(W1)[i];
        reinterpret_cast<float4*>(W2s)[i] = reinterpret_cast<const float4*>(W2)[i];
    }

    const int row0 = blockIdx.x * 64;
    #pragma unroll
    for (int i = tid; i < 64 * 16; i += 256) {
        const int r  = i >> 4;
        const int gr = row0 + r;
        float4 v = make_float4(0.f, 0.f, 0.f, 0.f);
        if (gr < N) v = reinterpret_cast<const float4*>(X)[(size_t)gr * 16 + (i & 15)];
        reinterpret_cast<float4*>(Xs)[i] = v;
    }

    // Fused histogram: spread-address int REDG, hidden under the FFMA2 loop.
    const int stride = gridDim.x * 256;
    for (int e = blockIdx.x * 256 + tid; e < E; e += stride)
        atomicAdd(&g_cnt[__ldg(rows + e)], 1);

    __syncthreads();

    const int rg  = (tid >> 4) * 4;
    const int cg4 = tid & 15;

    const u64* W1p = reinterpret_cast<const u64*>(W1s);
    const u64* W2p = reinterpret_cast<const u64*>(W2s);

    u64 acc1a[4], acc1b[4], acc2a[4], acc2b[4];
    #pragma unroll
    for (int i = 0; i < 4; ++i) { acc1a[i]=0; acc1b[i]=0; acc2a[i]=0; acc2b[i]=0; }

    #pragma unroll 8
    for (int k = 0; k < 64; ++k) {
        const u64 w1a = W1p[k * 32 + 2 * cg4];
        const u64 w1b = W1p[k * 32 + 2 * cg4 + 1];
        const u64 w2a = W2p[k * 32 + 2 * cg4];
        const u64 w2b = W2p[k * 32 + 2 * cg4 + 1];
        #pragma unroll
        for (int i = 0; i < 4; ++i) {
            const float x  = Xs[(rg + i) * 64 + k];
            const u64 xp  = pack2(x, x);
            const u64 xsq = mul2(xp, xp);
            acc1a[i] = fma2(xp,  w1a, acc1a[i]);
            acc1b[i] = fma2(xp,  w1b, acc1b[i]);
            acc2a[i] = fma2(xsq, w2a, acc2a[i]);
            acc2b[i] = fma2(xsq, w2b, acc2b[i]);
        }
    }

    const int cc = cg4 * 4;
    float4 bb;
    bb.x = __ldg(b1 + cc + 0) + __ldg(b2 + cc + 0);
    bb.y = __ldg(b1 + cc + 1) + __ldg(b2 + cc + 1);
    bb.z = __ldg(b1 + cc + 2) + __ldg(b2 + cc + 2);
    bb.w = __ldg(b1 + cc + 3) + __ldg(b2 + cc + 3);

    #pragma unroll
    for (int i = 0; i < 4; ++i) {
        const int gr = row0 + rg + i;
        if (gr < N) {
            float a10, a11, a12, a13, a20, a21, a22, a23;
            unpack2(acc1a[i], a10, a11);
            unpack2(acc1b[i], a12, a13);
            unpack2(acc2a[i], a20, a21);
            unpack2(acc2b[i], a22, a23);
            float4 o, q;
            o.x = a10 + bb.x;  q.x = a10 + a20;
            o.y = a11 + bb.y;  q.y = a11 + a21;
            o.z = a12 + bb.z;  q.z = a12 + a22;
            o.w = a13 + bb.w;  q.w = a13 + a23;
            reinterpret_cast<float4*>(out)[(size_t)gr * 16 + cg4] = o;
            reinterpret_cast<float4*>(g_Q)[(size_t)gr * 16 + cg4] = q;
        }
    }
}

// Spin barrier among nb co-resident blocks (nb <= 148: all wave-1 resident).
__device__ __forceinline__ void coop_barrier(int target) {
    __syncthreads();
    if (threadIdx.x == 0) {
        __threadfence();
        atomicAdd(&g_bar, 1);
        while (*(volatile int*)&g_bar < target) { }
    }
    __syncthreads();
}

// ---------------------------------------------------------------------------
// One-pass exclusive scan of g_cnt -> g_rowstart/g_cursor.
// nb=98 blocks x 1024 threads (1 cnt/thread); scan -> publish total ->
// barrier -> lane-parallel predecessor sum -> write. (R7 scan part, proven)
// ---------------------------------------------------------------------------
__global__ __launch_bounds__(1024) void gnn_scan(int N, int nb)
{
    __shared__ int ws[32];
    __shared__ int s_pfx;

    const int bid = blockIdx.x, tid = threadIdx.x;
    const int lane = tid & 31, wid = tid >> 5;
    const int i = bid * 1024 + tid;
    const int v = (i < N) ? g_cnt[i] : 0;

    int incl = v;
    #pragma unroll
    for (int off = 1; off < 32; off <<= 1) {
        int u = __shfl_up_sync(0xffffffffu, incl, off);
        if (lane >= off) incl += u;
    }
    if (lane == 31) ws[wid] = incl;
    __syncthreads();
    if (wid == 0) {
        int x = ws[lane];
        #pragma unroll
        for (int off = 1; off < 32; off <<= 1) {
            int u = __shfl_up_sync(0xffffffffu, x, off);
            if (lane >= off) x += u;
        }
        ws[lane] = x;
    }
    __syncthreads();
    const int excl = incl - v + (wid ? ws[wid - 1] : 0);

    if (tid == 1023) g_bsum[bid] = excl + v;        // block total
    coop_barrier(nb);

    if (wid == 0) {
        int s = 0;
        for (int j = lane; j < bid; j += 32) s += __ldcg(g_bsum + j);
        #pragma unroll
        for (int off = 16; off > 0; off >>= 1)
            s += __shfl_down_sync(0xffffffffu, s, off);
        if (lane == 0) s_pfx = s;
    }
    __syncthreads();

    if (i < N) {
        const int ex = s_pfx + excl;
        g_rowstart[i] = ex;
        g_cursor[i]   = ex;
    }
}

// ---------------------------------------------------------------------------
// Scatter edges into row bins (full E-thread parallelism).
// ---------------------------------------------------------------------------
__global__ __launch_bounds__(256) void gnn_scatter(
    const int* __restrict__ rows,
    const int* __restrict__ cols,
    const float* __restrict__ vals, int E)
{
    const int e = blockIdx.x * blockDim.x + threadIdx.x;
    if (e >= E) return;
    const int r   = __ldg(rows + e);
    const int pos = atomicAdd(&g_cursor[r], 1);
    g_edges[pos] = make_int2(__ldg(cols + e), __float_as_int(__ldg(vals + e)));
}

// ---------------------------------------------------------------------------
// CSR SpMM: 16 lanes per row, float4 per lane. (R6/R8 measured-best)
// ---------------------------------------------------------------------------
__global__ __launch_bounds__(256) void gnn_spmm_csr(float* __restrict__ out, int N)
{
    const int gid = blockIdx.x * blockDim.x + threadIdx.x;
    const int row = gid >> 4;
    if (row >= N) return;
    const int lane16 = gid & 15;

    const int start = __ldg(g_rowstart + row);
    const int end   = __ldg(g_cursor + row);
    if (end <= start) return;

    const float4* __restrict__ Q4 = reinterpret_cast<const float4*>(g_Q);
    float4 acc = make_float4(0.f, 0.f, 0.f, 0.f);

    int j = start;
    for (; j + 3 < end; j += 4) {
        const int2 cv0 = __ldg(g_edges + j);
        const int2 cv1 = __ldg(g_edges + j + 1);
        const int2 cv2 = __ldg(g_edges + j + 2);
        const int2 cv3 = __ldg(g_edges + j + 3);
        const float4 q0 = __ldg(Q4 + (size_t)cv0.x * 16 + lane16);
        const float4 q1 = __ldg(Q4 + (size_t)cv1.x * 16 + lane16);
        const float4 q2 = __ldg(Q4 + (size_t)cv2.x * 16 + lane16);
        const float4 q3 = __ldg(Q4 + (size_t)cv3.x * 16 + lane16);
        const float v0 = __int_as_float(cv0.y);
        const float v1 = __int_as_float(cv1.y);
        const float v2 = __int_as_float(cv2.y);
        const float v3 = __int_as_float(cv3.y);
        acc.x = fmaf(v0, q0.x, acc.x); acc.y = fmaf(v0, q0.y, acc.y);
        acc.z = fmaf(v0, q0.z, acc.z); acc.w = fmaf(v0, q0.w, acc.w);
        acc.x = fmaf(v1, q1.x, acc.x); acc.y = fmaf(v1, q1.y, acc.y);
        acc.z = fmaf(v1, q1.z, acc.z); acc.w = fmaf(v1, q1.w, acc.w);
        acc.x = fmaf(v2, q2.x, acc.x); acc.y = fmaf(v2, q2.y, acc.y);
        acc.z = fmaf(v2, q2.z, acc.z); acc.w = fmaf(v2, q2.w, acc.w);
        acc.x = fmaf(v3, q3.x, acc.x); acc.y = fmaf(v3, q3.y, acc.y);
        acc.z = fmaf(v3, q3.z, acc.z); acc.w = fmaf(v3, q3.w, acc.w);
    }
    for (; j < end; ++j) {
        const int2 cv = __ldg(g_edges + j);
        const float4 q = __ldg(Q4 + (size_t)cv.x * 16 + lane16);
        const float v = __int_as_float(cv.y);
        acc.x = fmaf(v, q.x, acc.x); acc.y = fmaf(v, q.y, acc.y);
        acc.z = fmaf(v, q.z, acc.z); acc.w = fmaf(v, q.w, acc.w);
    }

    float4* orow = reinterpret_cast<float4*>(out) + (size_t)row * 16 + lane16;
    float4 o = *orow;
    o.x += acc.x; o.y += acc.y; o.z += acc.z; o.w += acc.w;
    *orow = o;
}

extern "C" void kernel_launch(void* const* d_in, const int* in_sizes, int n_in,
                              void* d_out, int out_size)
{
    const int*   rows = (const int*)  d_in[0];
    const int*   cols = (const int*)  d_in[1];
    const float* vals = (const float*)d_in[2];
    const float* X    = (const float*)d_in[3];
    const float* W1   = (const float*)d_in[4];
    const float* b1   = (const float*)d_in[5];
    const float* W2   = (const float*)d_in[6];
    const float* b2   = (const float*)d_in[7];
    float* out = (float*)d_out;

    const int E = in_sizes[0];
    const int N = in_sizes[3] / FDIM;
    const int nb = (N + 1023) / 1024;           // 98 (< 148, co-resident)

    cudaFuncSetAttribute(gnn_dense_hist, cudaFuncAttributeMaxDynamicSharedMemorySize, 49152);

    void* p = nullptr;
    cudaGetSymbolAddress(&p, g_cnt);
    cudaMemsetAsync(p, 0, (size_t)N * sizeof(int));
    cudaGetSymbolAddress(&p, g_bar);
    cudaMemsetAsync(p, 0, sizeof(int));

    const int blocksD = (N + 63) / 64;
    gnn_dense_hist<<<blocksD, 256, 49152>>>(X, W1, b1, W2, b2, rows, out, N, E);

    gnn_scan<<<nb, 1024>>>(N, nb);

    gnn_scatter<<<(E + 255) / 256, 256>>>(rows, cols, vals, E);

    const long long work = (long long)N * 16;
    gnn_spmm_csr<<<(int)((work + 255) / 256), 256>>>(out, N);
}

// round 12
// speedup vs baseline: 1.1261x; 1.0596x over previous
#include <cuda_runtime.h>

#define MAX_N 100000
#define MAX_E 1200000
#define MAX_EP (MAX_E + 3 * MAX_N)   // padded bins: each row rounded up to 4
#define FDIM 64

__device__ float g_Q[(size_t)MAX_N * FDIM];      // Q = X@W1 + (X*X)@W2
__device__ int   g_cnt[MAX_N];                   // per-row edge count
__device__ int   g_rowstart[MAX_N];              // exclusive scan of padded counts
__device__ int   g_cursor[MAX_N];                // scatter cursor
__device__ int2  g_edges[MAX_EP];                // binned (col, val), zero-padded to x4
__device__ int   g_bsum[128];                    // block sums for the scan

// ---- packed f32x2 helpers (sm_103a FFMA2: 2 fp32 FMAs / issue slot) ----
typedef unsigned long long u64;
__device__ __forceinline__ u64 pack2(float lo, float hi) {
    u64 r; asm("mov.b64 %0, {%1, %2};" : "=l"(r) : "f"(lo), "f"(hi)); return r;
}
__device__ __forceinline__ void unpack2(u64 p, float& lo, float& hi) {
    asm("mov.b64 {%0, %1}, %2;" : "=f"(lo), "=f"(hi) : "l"(p));
}
__device__ __forceinline__ u64 fma2(u64 a, u64 b, u64 c) {
    u64 d; asm("fma.rn.f32x2 %0, %1, %2, %3;" : "=l"(d) : "l"(a), "l"(b), "l"(c)); return d;
}
__device__ __forceinline__ u64 mul2(u64 a, u64 b) {
    u64 d; asm("mul.rn.f32x2 %0, %1, %2;" : "=l"(d) : "l"(a), "l"(b)); return d;
}

// ---------------------------------------------------------------------------
// Dense GEMM (f32x2) + fused histogram. 64-row tile, 4 rows/thread,
// 48KB smem, 3 blocks/SM. (R8 measured-best, byte-identical)
// ---------------------------------------------------------------------------
__global__ __launch_bounds__(256, 3) void gnn_dense_hist(
    const float* __restrict__ X,
    const float* __restrict__ W1, const float* __restrict__ b1,
    const float* __restrict__ W2, const float* __restrict__ b2,
    const int* __restrict__ rows,
    float* __restrict__ out, int N, int E)
{
    extern __shared__ float smem[];
    float* W1s = smem;          // 64*64 = 16KB
    float* W2s = smem + 4096;   // 16KB
    float* Xs  = smem + 8192;   // 64*64 = 16KB

    const int tid = threadIdx.x;

    #pragma unroll
    for (int i = tid; i < 1024; i += 256) {
        reinterpret_cast<float4*>(W1s)[i] = reinterpret_cast<const float4*>(W1)[i];
        reinterpret_cast<float4*>(W2s)[i] = reinterpret_cast<const float4*>(W2)[i];
    }

    const int row0 = blockIdx.x * 64;
    #pragma unroll
    for (int i = tid; i < 64 * 16; i += 256) {
        const int r  = i >> 4;
        const int gr = row0 + r;
        float4 v = make_float4(0.f, 0.f, 0.f, 0.f);
        if (gr < N) v = reinterpret_cast<const float4*>(X)[(size_t)gr * 16 + (i & 15)];
        reinterpret_cast<float4*>(Xs)[i] = v;
    }

    // Fused histogram: spread-address int REDG, hidden under the FFMA2 loop.
    const int stride = gridDim.x * 256;
    for (int e = blockIdx.x * 256 + tid; e < E; e += stride)
        atomicAdd(&g_cnt[__ldg(rows + e)], 1);

    __syncthreads();

    const int rg  = (tid >> 4) * 4;
    const int cg4 = tid & 15;

    const u64* W1p = reinterpret_cast<const u64*>(W1s);
    const u64* W2p = reinterpret_cast<const u64*>(W2s);

    u64 acc1a[4], acc1b[4], acc2a[4], acc2b[4];
    #pragma unroll
    for (int i = 0; i < 4; ++i) { acc1a[i]=0; acc1b[i]=0; acc2a[i]=0; acc2b[i]=0; }

    #pragma unroll 8
    for (int k = 0; k < 64; ++k) {
        const u64 w1a = W1p[k * 32 + 2 * cg4];
        const u64 w1b = W1p[k * 32 + 2 * cg4 + 1];
        const u64 w2a = W2p[k * 32 + 2 * cg4];
        const u64 w2b = W2p[k * 32 + 2 * cg4 + 1];
        #pragma unroll
        for (int i = 0; i < 4; ++i) {
            const float x  = Xs[(rg + i) * 64 + k];
            const u64 xp  = pack2(x, x);
            const u64 xsq = mul2(xp, xp);
            acc1a[i] = fma2(xp,  w1a, acc1a[i]);
            acc1b[i] = fma2(xp,  w1b, acc1b[i]);
            acc2a[i] = fma2(xsq, w2a, acc2a[i]);
            acc2b[i] = fma2(xsq, w2b, acc2b[i]);
        }
    }

    const int cc = cg4 * 4;
    float4 bb;
    bb.x = __ldg(b1 + cc + 0) + __ldg(b2 + cc + 0);
    bb.y = __ldg(b1 + cc + 1) + __ldg(b2 + cc + 1);
    bb.z = __ldg(b1 + cc + 2) + __ldg(b2 + cc + 2);
    bb.w = __ldg(b1 + cc + 3) + __ldg(b2 + cc + 3);

    #pragma unroll
    for (int i = 0; i < 4; ++i) {
        const int gr = row0 + rg + i;
        if (gr < N) {
            float a10, a11, a12, a13, a20, a21, a22, a23;
            unpack2(acc1a[i], a10, a11);
            unpack2(acc1b[i], a12, a13);
            unpack2(acc2a[i], a20, a21);
            unpack2(acc2b[i], a22, a23);
            float4 o, q;
            o.x = a10 + bb.x;  q.x = a10 + a20;
            o.y = a11 + bb.y;  q.y = a11 + a21;
            o.z = a12 + bb.z;  q.z = a12 + a22;
            o.w = a13 + bb.w;  q.w = a13 + a23;
            reinterpret_cast<float4*>(out)[(size_t)gr * 16 + cg4] = o;
            reinterpret_cast<float4*>(g_Q)[(size_t)gr * 16 + cg4] = q;
        }
    }
}

// ---------------------------------------------------------------------------
// Scan stage (R8 structure) over PADDED counts vp = (cnt+3)&~3.
// ---------------------------------------------------------------------------
__device__ __forceinline__ int warp_incl_scan(int v) {
    #pragma unroll
    for (int off = 1; off < 32; off <<= 1) {
        int u = __shfl_up_sync(0xffffffffu, v, off);
        if ((threadIdx.x & 31) >= off) v += u;
    }
    return v;
}

__global__ __launch_bounds__(1024) void scan_blocksums(int N) {
    const int i = blockIdx.x * 1024 + threadIdx.x;
    int v = (i < N) ? ((g_cnt[i] + 3) & ~3) : 0;
    #pragma unroll
    for (int off = 16; off > 0; off >>= 1)
        v += __shfl_down_sync(0xffffffffu, v, off);
    __shared__ int ws[32];
    const int lane = threadIdx.x & 31, wid = threadIdx.x >> 5;
    if (lane == 0) ws[wid] = v;
    __syncthreads();
    if (wid == 0) {
        int x = ws[lane];
        #pragma unroll
        for (int off = 16; off > 0; off >>= 1)
            x += __shfl_down_sync(0xffffffffu, x, off);
        if (lane == 0) g_bsum[blockIdx.x] = x;
    }
}

__global__ __launch_bounds__(128) void scan_bsums(int nb) {
    __shared__ int s[128];
    const int t = threadIdx.x;
    s[t] = (t < nb) ? g_bsum[t] : 0;
    __syncthreads();
    #pragma unroll
    for (int off = 1; off < 128; off <<= 1) {
        int v = (t >= off) ? s[t - off] : 0;
        __syncthreads();
        s[t] += v;
        __syncthreads();
    }
    if (t < nb) g_bsum[t] = s[t];
}

__global__ __launch_bounds__(1024) void scan_write(int N) {
    const int t = threadIdx.x, b = blockIdx.x;
    const int i = b * 1024 + t;
    const int cnt = (i < N) ? g_cnt[i] : 0;
    const int vp  = (cnt + 3) & ~3;
    const int lane = t & 31, wid = t >> 5;
    int inc = warp_incl_scan(vp);
    __shared__ int ws[32];
    if (lane == 31) ws[wid] = inc;
    __syncthreads();
    if (wid == 0) {
        int x = ws[lane];
        x = warp_incl_scan(x);
        ws[lane] = x;
    }
    __syncthreads();
    int excl = inc - vp + (wid ? ws[wid - 1] : 0) + (b ? g_bsum[b - 1] : 0);
    if (i < N) {
        g_rowstart[i] = excl;
        g_cursor[i]   = excl;
        // Pre-zero the <=3 padding slots (scatter never touches them).
        const int2 z = make_int2(0, 0);
        for (int p = excl + cnt; p < excl + vp; ++p) g_edges[p] = z;
    }
}

__global__ __launch_bounds__(256) void gnn_scatter(
    const int* __restrict__ rows,
    const int* __restrict__ cols,
    const float* __restrict__ vals, int E)
{
    const int e = blockIdx.x * blockDim.x + threadIdx.x;
    if (e >= E) return;
    const int r   = __ldg(rows + e);
    const int pos = atomicAdd(&g_cursor[r], 1);
    g_edges[pos] = make_int2(__ldg(cols + e), __float_as_int(__ldg(vals + e)));
}

// ---------------------------------------------------------------------------
// CSR SpMM: 16 lanes per row, float4 per lane; bins padded to x4 so the
// loop is guard-free; next chunk's edges prefetched before this chunk's
// gathers -> exposed latency per iteration = gather only.
// ---------------------------------------------------------------------------
__global__ __launch_bounds__(256) void gnn_spmm_csr(float* __restrict__ out, int N)
{
    const int gid = blockIdx.x * blockDim.x + threadIdx.x;
    const int row = gid >> 4;
    if (row >= N) return;
    const int lane16 = gid & 15;

    const int start = __ldg(g_rowstart + row);
    const int end   = __ldg(g_cursor + row);      // = start + cnt
    const int deg   = end - start;
    if (deg <= 0) return;
    int iters = (deg + 3) >> 2;

    const float4* __restrict__ Q4 = reinterpret_cast<const float4*>(g_Q);
    const int2* ep = g_edges + start;

    int2 c0 = __ldg(ep + 0), c1 = __ldg(ep + 1);
    int2 c2 = __ldg(ep + 2), c3 = __ldg(ep + 3);

    float4 acc = make_float4(0.f, 0.f, 0.f, 0.f);

    while (--iters > 0) {
        ep += 4;
        const int2 n0 = __ldg(ep + 0), n1 = __ldg(ep + 1);
        const int2 n2 = __ldg(ep + 2), n3 = __ldg(ep + 3);

        const float4 q0 = __ldg(Q4 + (size_t)c0.x * 16 + lane16);
        const float4 q1 = __ldg(Q4 + (size_t)c1.x * 16 + lane16);
        const float4 q2 = __ldg(Q4 + (size_t)c2.x * 16 + lane16);
        const float4 q3 = __ldg(Q4 + (size_t)c3.x * 16 + lane16);
        const float v0 = __int_as_float(c0.y);
        const float v1 = __int_as_float(c1.y);
        const float v2 = __int_as_float(c2.y);
        const float v3 = __int_as_float(c3.y);
        acc.x = fmaf(v0, q0.x, acc.x); acc.y = fmaf(v0, q0.y, acc.y);
        acc.z = fmaf(v0, q0.z, acc.z); acc.w = fmaf(v0, q0.w, acc.w);
        acc.x = fmaf(v1, q1.x, acc.x); acc.y = fmaf(v1, q1.y, acc.y);
        acc.z = fmaf(v1, q1.z, acc.z); acc.w = fmaf(v1, q1.w, acc.w);
        acc.x = fmaf(v2, q2.x, acc.x); acc.y = fmaf(v2, q2.y, acc.y);
        acc.z = fmaf(v2, q2.z, acc.z); acc.w = fmaf(v2, q2.w, acc.w);
        acc.x = fmaf(v3, q3.x, acc.x); acc.y = fmaf(v3, q3.y, acc.y);
        acc.z = fmaf(v3, q3.z, acc.z); acc.w = fmaf(v3, q3.w, acc.w);

        c0 = n0; c1 = n1; c2 = n2; c3 = n3;
    }

    {   // final chunk (padding edges have val=0 -> no-op FMAs)
        const float4 q0 = __ldg(Q4 + (size_t)c0.x * 16 + lane16);
        const float4 q1 = __ldg(Q4 + (size_t)c1.x * 16 + lane16);
        const float4 q2 = __ldg(Q4 + (size_t)c2.x * 16 + lane16);
        const float4 q3 = __ldg(Q4 + (size_t)c3.x * 16 + lane16);
        const float v0 = __int_as_float(c0.y);
        const float v1 = __int_as_float(c1.y);
        const float v2 = __int_as_float(c2.y);
        const float v3 = __int_as_float(c3.y);
        acc.x = fmaf(v0, q0.x, acc.x); acc.y = fmaf(v0, q0.y, acc.y);
        acc.z = fmaf(v0, q0.z, acc.z); acc.w = fmaf(v0, q0.w, acc.w);
        acc.x = fmaf(v1, q1.x, acc.x); acc.y = fmaf(v1, q1.y, acc.y);
        acc.z = fmaf(v1, q1.z, acc.z); acc.w = fmaf(v1, q1.w, acc.w);
        acc.x = fmaf(v2, q2.x, acc.x); acc.y = fmaf(v2, q2.y, acc.y);
        acc.z = fmaf(v2, q2.z, acc.z); acc.w = fmaf(v2, q2.w, acc.w);
        acc.x = fmaf(v3, q3.x, acc.x); acc.y = fmaf(v3, q3.y, acc.y);
        acc.z = fmaf(v3, q3.z, acc.z); acc.w = fmaf(v3, q3.w, acc.w);
    }

    float4* orow = reinterpret_cast<float4*>(out) + (size_t)row * 16 + lane16;
    float4 o = *orow;
    o.x += acc.x; o.y += acc.y; o.z += acc.z; o.w += acc.w;
    *orow = o;
}

extern "C" void kernel_launch(void* const* d_in, const int* in_sizes, int n_in,
                              void* d_out, int out_size)
{
    const int*   rows = (const int*)  d_in[0];
    const int*   cols = (const int*)  d_in[1];
    const float* vals = (const float*)d_in[2];
    const float* X    = (const float*)d_in[3];
    const float* W1   = (const float*)d_in[4];
    const float* b1   = (const float*)d_in[5];
    const float* W2   = (const float*)d_in[6];
    const float* b2   = (const float*)d_in[7];
    float* out = (float*)d_out;

    const int E = in_sizes[0];
    const int N = in_sizes[3] / FDIM;

    cudaFuncSetAttribute(gnn_dense_hist, cudaFuncAttributeMaxDynamicSharedMemorySize, 49152);

    void* p = nullptr;
    cudaGetSymbolAddress(&p, g_cnt);
    cudaMemsetAsync(p, 0, (size_t)N * sizeof(int));

    const int blocksD = (N + 63) / 64;
    gnn_dense_hist<<<blocksD, 256, 49152>>>(X, W1, b1, W2, b2, rows, out, N, E);

    const int nb = (N + 1023) / 1024;
    scan_blocksums<<<nb, 1024>>>(N);
    scan_bsums<<<1, 128>>>(nb);
    scan_write<<<nb, 1024>>>(N);

    gnn_scatter<<<(E + 255) / 256, 256>>>(rows, cols, vals, E);

    const long long work = (long long)N * 16;
    gnn_spmm_csr<<<(int)((work + 255) / 256), 256>>>(out, N);
}